// round 15
// baseline (speedup 1.0000x reference)
#include <cuda_runtime.h>
#include <cuda_bf16.h>
#include <math.h>
#include <stdint.h>

#define EXER_N 10000
#define STU_N  20000
#define DD     128
#define HH     3
#define HD     384
#define CAP    96
#define BATCH  2048

#define SZF(x) ((size_t)(x))

// ---------------- scratch arena ---------------------------------------------
static constexpr size_t O_Wz3   = 0;
static constexpr size_t O_Wzc   = O_Wz3   + SZF(5)*DD*HD;
static constexpr size_t O_Wlr   = O_Wzc   + SZF(5)*DD*DD;
static constexpr size_t O_bz    = O_Wlr   + SZF(5)*DD*8;
static constexpr size_t O_zE    = O_bz    + SZF(5)*DD;
static constexpr size_t O_elE   = O_zE    + SZF(3)*EXER_N*DD;
static constexpr size_t O_zlE   = O_elE   + SZF(3)*EXER_N*4;
static constexpr size_t O_erD   = O_zlE   + SZF(3)*EXER_N;
static constexpr size_t O_zrD   = O_erD   + SZF(EXER_N)*4;
static constexpr size_t O_ABCD  = O_zrD   + SZF(EXER_N);
static constexpr size_t O_ABPCD = O_ABCD  + SZF(STU_N)*4*DD;
static constexpr size_t O_stu1  = O_ABPCD + SZF(STU_N)*4*DD;
static constexpr size_t O_stu1p = O_stu1  + SZF(STU_N)*DD;
static constexpr size_t O_XYX   = O_stu1p + SZF(STU_N)*DD;
static constexpr size_t O_XYP   = O_XYX   + SZF(STU_N)*2*DD;
static constexpr size_t O_stu2  = O_XYP   + SZF(STU_N)*2*DD;
static constexpr size_t O_stu2p = O_stu2  + SZF(STU_N)*DD;
static constexpr size_t O_nb    = O_stu2p + SZF(STU_N)*DD;
static constexpr size_t O_nbp   = O_nb    + SZF(BATCH)*DD;
static constexpr size_t O_S     = O_nbp   + SZF(BATCH)*DD;
static constexpr size_t O_lossd = O_S     + DD;
static constexpr size_t O_part  = O_lossd + 16;
static constexpr size_t O_lpart = O_part  + SZF(16)*DD;
static constexpr size_t O_SCR   = O_lpart + BATCH;
static constexpr size_t SC_zS3  = 0;
static constexpr size_t SC_TOT  = SC_zS3 + SZF(STU_N)*HD;
static constexpr size_t F_TOT   = O_SCR + 4*SC_TOT;

static constexpr size_t OH_zE3  = 0;
static constexpr size_t OH_zE   = OH_zE3 + SZF(3)*EXER_N*HD;
static constexpr size_t H_TOT   = OH_zE  + SZF(3)*EXER_N*DD;

static constexpr size_t OI_adj  = 0;
static constexpr size_t OI_cnt  = SZF(3)*STU_N*CAP;
static constexpr size_t I_TOT   = OI_cnt + SZF(3)*STU_N;

__device__ __align__(256) float          g_farena[F_TOT];
__device__ __align__(256) __nv_bfloat16  g_harena[H_TOT];
__device__ __align__(256) int            g_iarena[I_TOT];

// ---------------- batched pointer structs ------------------------------------
struct GB {
    const float*    A[4];
    const float*    B[4];
    float*          C[4];
    float*          C2[4];
    __nv_bfloat16*  Ch[4];
    const float*    bias[4];
    const float*    addm[4];
};
struct ESB {
    const float* x[4];
    const float* wlr[4];
    float*       el[4];
    float*       er[4];
};
struct ZZB {
    const float* z[4];
    const float* aW[4];
    float*       zl[4];
    float*       zr[4];
};
struct FZB {                      // fused GAT phase B (3 slots per block)
    const int*           adj[4];
    const int*           cnt[4];
    const float*         x[4];
    const float*         wlr[4];
    const float*         elE[4];
    const __nv_bfloat16* zE3[4];
    const float*         zS3[4];
    const __nv_bfloat16* zE[4];
    const float*         zlE[4];
    const float*         bz[4];
    const float*         aW[4];
    float*               out[4];
    float*               out2[4];
};
struct FZM {                      // fused GAT phase D (2 slots x 2 branches)
    const int*           adj[2];
    const int*           cnt[2];
    const float*         wlr[2];
    const float*         elE[2];
    const __nv_bfloat16* zE3[2];
    const __nv_bfloat16* zE[2];
    const float*         zlE[2];
    const float*         bz[2];
    const float*         aW[2];
    const float*         xX[2];
    const float*         xP[2];
    const float*         zS3X[2];
    const float*         zS3P[2];
    float*               outX[2];
    float*               outP[2];
};
struct ADJB {
    const int* src[3];
    const int* dst[3];
    int        ecnt[3];
    int*       adj[3];
    int*       cnt[3];
};
struct NRB {
    const float* emb[2];
    float*       out[2];
};

// ---------------- TF32 tensor-core batched GEMM (128x128, best config) -------
__device__ __forceinline__ uint32_t f2tf32(float x) {
    uint32_t u;
    asm("cvt.rna.tf32.f32 %0, %1;" : "=r"(u) : "f"(x));
    return u;
}
__device__ __forceinline__ void mma_tf32(float* c, uint32_t a0, uint32_t a1,
                                         uint32_t a2, uint32_t a3,
                                         uint32_t b0, uint32_t b1) {
    asm volatile(
        "mma.sync.aligned.m16n8k8.row.col.f32.tf32.tf32.f32 "
        "{%0,%1,%2,%3}, {%4,%5,%6,%7}, {%8,%9}, {%0,%1,%2,%3};"
        : "+f"(c[0]), "+f"(c[1]), "+f"(c[2]), "+f"(c[3])
        : "r"(a0), "r"(a1), "r"(a2), "r"(a3), "r"(b0), "r"(b1));
}

#define SPAD 136

__global__ __launch_bounds__(256, 2)
void tgemm_b(GB g, int lda, int ldc, int ldadd, int M, int N, int K)
{
    const int z = blockIdx.z;
    const float* __restrict__ A    = g.A[z];
    const float* __restrict__ B    = g.B[z];
    float*                    C    = g.C[z];
    float*                    C2   = g.C2[z];
    __nv_bfloat16*            Ch   = g.Ch[z];
    const float*              bias = g.bias[z];
    const float*              addm = g.addm[z];

    __shared__ uint32_t As[2][16][SPAD];
    __shared__ uint32_t Bs[2][16][SPAD];

    const int tid  = threadIdx.x;
    const int bm   = blockIdx.y * 128;
    const int bn   = blockIdx.x * 128;
    const int lane = tid & 31;
    const int gid  = lane >> 2;
    const int tg   = lane & 3;
    const int warp = tid >> 5;
    const int wm   = warp & 3;
    const int wn   = warp >> 2;

    float acc[2][8][4];
#pragma unroll
    for (int mt = 0; mt < 2; mt++)
#pragma unroll
        for (int nt = 0; nt < 8; nt++)
#pragma unroll
            for (int c = 0; c < 4; c++) acc[mt][nt][c] = 0.f;

    const int am  = tid >> 1;
    const int ak0 = (tid & 1) * 4;
    const int brr = tid >> 5;
    const int bcc = (tid & 31) * 4;

    const bool arow_ok = (bm + am < M);
    float4 av0, av1, bv0, bv1;

    auto ldtile = [&](int k0) {
        av0 = arow_ok ? *(const float4*)(A + (size_t)(bm + am) * lda + k0 + ak0)
                      : make_float4(0.f, 0.f, 0.f, 0.f);
        av1 = arow_ok ? *(const float4*)(A + (size_t)(bm + am) * lda + k0 + 8 + ak0)
                      : make_float4(0.f, 0.f, 0.f, 0.f);
        bv0 = *(const float4*)(B + (size_t)(k0 + brr) * N + bn + bcc);
        bv1 = *(const float4*)(B + (size_t)(k0 + 8 + brr) * N + bn + bcc);
    };
    auto sttile = [&](int p) {
        As[p][ak0 + 0][am] = f2tf32(av0.x);
        As[p][ak0 + 1][am] = f2tf32(av0.y);
        As[p][ak0 + 2][am] = f2tf32(av0.z);
        As[p][ak0 + 3][am] = f2tf32(av0.w);
        As[p][8 + ak0 + 0][am] = f2tf32(av1.x);
        As[p][8 + ak0 + 1][am] = f2tf32(av1.y);
        As[p][8 + ak0 + 2][am] = f2tf32(av1.z);
        As[p][8 + ak0 + 3][am] = f2tf32(av1.w);
        uint4 t0 = make_uint4(f2tf32(bv0.x), f2tf32(bv0.y), f2tf32(bv0.z), f2tf32(bv0.w));
        uint4 t1 = make_uint4(f2tf32(bv1.x), f2tf32(bv1.y), f2tf32(bv1.z), f2tf32(bv1.w));
        *(uint4*)(&Bs[p][brr][bcc]) = t0;
        *(uint4*)(&Bs[p][8 + brr][bcc]) = t1;
    };

    ldtile(0);
    sttile(0);

    const int nt_tiles = K / 16;
    for (int kt = 0; kt < nt_tiles; kt++) {
        const int p = kt & 1;
        const bool more = (kt + 1 < nt_tiles);
        if (more) ldtile((kt + 1) * 16);
        __syncthreads();

#pragma unroll
        for (int ks = 0; ks < 2; ks++) {
            const int kk = ks * 8;
            uint32_t bf[8][2];
#pragma unroll
            for (int nt = 0; nt < 8; nt++) {
                const int n0 = wn * 64 + nt * 8 + gid;
                bf[nt][0] = Bs[p][kk + tg][n0];
                bf[nt][1] = Bs[p][kk + tg + 4][n0];
            }
#pragma unroll
            for (int mt = 0; mt < 2; mt++) {
                const int m0 = wm * 32 + mt * 16;
                uint32_t a0 = As[p][kk + tg][m0 + gid];
                uint32_t a1 = As[p][kk + tg][m0 + gid + 8];
                uint32_t a2 = As[p][kk + tg + 4][m0 + gid];
                uint32_t a3 = As[p][kk + tg + 4][m0 + gid + 8];
#pragma unroll
                for (int nt = 0; nt < 8; nt++)
                    mma_tf32(acc[mt][nt], a0, a1, a2, a3, bf[nt][0], bf[nt][1]);
            }
        }
        if (more) sttile(p ^ 1);
    }

#pragma unroll
    for (int mt = 0; mt < 2; mt++) {
        const int r0 = bm + wm * 32 + mt * 16 + gid;
        const int r1 = r0 + 8;
#pragma unroll
        for (int nt = 0; nt < 8; nt++) {
            const int n = bn + wn * 64 + nt * 8 + tg * 2;
            float2 v0 = make_float2(acc[mt][nt][0], acc[mt][nt][1]);
            float2 v1 = make_float2(acc[mt][nt][2], acc[mt][nt][3]);
            if (bias) {
                float b0 = bias[n], b1 = bias[n + 1];
                v0.x += b0; v0.y += b1;
                v1.x += b0; v1.y += b1;
            }
            if (r0 < M) {
                float2 o = v0;
                if (addm) {
                    const float2 ad = *(const float2*)(addm + (size_t)r0 * ldadd + n);
                    o.x += ad.x; o.y += ad.y;
                }
                if (C)  *(float2*)(C + (size_t)r0 * ldc + n) = o;
                if (C2) *(float2*)(C2 + (size_t)r0 * ldc + n) = o;
                if (Ch) *(__nv_bfloat162*)(Ch + (size_t)r0 * ldc + n) =
                            __floats2bfloat162_rn(o.x, o.y);
            }
            if (r1 < M) {
                float2 o = v1;
                if (addm) {
                    const float2 ad = *(const float2*)(addm + (size_t)r1 * ldadd + n);
                    o.x += ad.x; o.y += ad.y;
                }
                if (C)  *(float2*)(C + (size_t)r1 * ldc + n) = o;
                if (C2) *(float2*)(C2 + (size_t)r1 * ldc + n) = o;
                if (Ch) *(__nv_bfloat162*)(Ch + (size_t)r1 * ldc + n) =
                            __floats2bfloat162_rn(o.x, o.y);
            }
        }
    }
}

// ---------------- weight precompute (exact fp32) -----------------------------
__global__ void wz_kernel(const float* __restrict__ gatW, const float* __restrict__ fcW,
                          float* __restrict__ Wz3, float* __restrict__ Wzc) {
    int p = blockIdx.y;
    int k = blockIdx.x;
    int n = threadIdx.x;
    const float* Wrow = gatW + ((size_t)p * DD + k) * HD;
    const float* F = fcW + (size_t)p * HD * DD;
    __shared__ float wr[HD];
    for (int i = n; i < HD; i += DD) wr[i] = Wrow[i];
    __syncthreads();
    float a0 = 0.f, a1 = 0.f, a2 = 0.f;
    for (int d = 0; d < DD; d++) {
        a0 += wr[d]          * F[(size_t)d * DD + n];
        a1 += wr[DD + d]     * F[(size_t)(DD + d) * DD + n];
        a2 += wr[2 * DD + d] * F[(size_t)(2 * DD + d) * DD + n];
    }
    size_t o = ((size_t)p * DD + k) * HD;
    Wz3[o + n] = a0; Wz3[o + DD + n] = a1; Wz3[o + 2 * DD + n] = a2;
    Wzc[((size_t)p * DD + k) * DD + n] = a0 + a1 + a2;
}

__global__ void wlr_kernel(const float* __restrict__ gatW, const float* __restrict__ al,
                           const float* __restrict__ ar, float* __restrict__ Wlr) {
    int p = blockIdx.x;
    int k = threadIdx.x;
    __shared__ float sal[HD], sar[HD];
    for (int i = k; i < HD; i += DD) {
        sal[i] = al[(size_t)p * HD + i];
        sar[i] = ar[(size_t)p * HD + i];
    }
    __syncthreads();
    const float* Wrow = gatW + ((size_t)p * DD + k) * HD;
    float o[6] = {0.f, 0.f, 0.f, 0.f, 0.f, 0.f};
    for (int h = 0; h < 3; h++)
        for (int d = 0; d < DD; d++) {
            float w = Wrow[h * DD + d];
            o[h]     += w * sal[h * DD + d];
            o[3 + h] += w * sar[h * DD + d];
        }
#pragma unroll
    for (int i = 0; i < 6; i++) Wlr[((size_t)p * DD + k) * 8 + i] = o[i];
}

__global__ void bz_kernel(const float* __restrict__ gb, const float* __restrict__ fcW,
                          const float* __restrict__ fcb, float* __restrict__ bz) {
    int p = blockIdx.x, n = threadIdx.x;
    const float* g = gb + (size_t)p * HD;
    const float* W = fcW + (size_t)p * HD * DD;
    float s = fcb[(size_t)p * DD + n];
    for (int k = 0; k < HD; k++) s += g[k] * W[(size_t)k * DD + n];
    bz[(size_t)p * DD + n] = s;
}

// ---------------- small batched kernels ---------------------------------------
__global__ void zero_int(int* p, int n) {
    int i = blockIdx.x * blockDim.x + threadIdx.x;
    if (i < n) p[i] = 0;
}
__global__ void build_adj_b(ADJB g) {
    int z = blockIdx.y;
    int i = blockIdx.x * blockDim.x + threadIdx.x;
    if (i >= g.ecnt[z]) return;
    int d = g.dst[z][i];
    if (d < EXER_N) return;
    int dl = d - EXER_N;
    int slot = atomicAdd(&g.cnt[z][dl], 1);
    if (slot < CAP) g.adj[z][(size_t)dl * CAP + slot] = g.src[z][i];
}

__global__ void escore_b(ESB g) {
    int z = blockIdx.y;
    int n = blockIdx.x, t = threadIdx.x;
    float xv = g.x[z][(size_t)n * DD + t];
    const float* w = g.wlr[z] + (size_t)t * 8;
    float o[6];
#pragma unroll
    for (int i = 0; i < 6; i++) o[i] = xv * w[i];
#pragma unroll
    for (int off = 16; off; off >>= 1)
#pragma unroll
        for (int i = 0; i < 6; i++) o[i] += __shfl_xor_sync(0xffffffffu, o[i], off);
    __shared__ float red[4][6];
    int wp = t >> 5;
    if ((t & 31) == 0)
#pragma unroll
        for (int i = 0; i < 6; i++) red[wp][i] = o[i];
    __syncthreads();
    if (t < 6) {
        float v = red[0][t] + red[1][t] + red[2][t] + red[3][t];
        if (t < 3) g.el[z][(size_t)n * 4 + t] = v;
        else       g.er[z][(size_t)n * 4 + (t - 3)] = v;
    }
}

__global__ void zlzr_b(ZZB g) {
    int z = blockIdx.y;
    int n = blockIdx.x, t = threadIdx.x;
    float v = g.z[z][(size_t)n * DD + t];
    float a = v * g.aW[z][t];
    float b = v * g.aW[z][DD + t];
#pragma unroll
    for (int off = 16; off; off >>= 1) {
        a += __shfl_xor_sync(0xffffffffu, a, off);
        b += __shfl_xor_sync(0xffffffffu, b, off);
    }
    __shared__ float red[4][2];
    int w = t >> 5;
    if ((t & 31) == 0) { red[w][0] = a; red[w][1] = b; }
    __syncthreads();
    if (t < 2) {
        float v2 = red[0][t] + red[1][t] + red[2][t] + red[3][t];
        if (t == 0) g.zl[z][n] = v2; else g.zr[z][n] = v2;
    }
}

// ---------------- fused GAT, phase B: 3 slots per block -----------------------
__global__ void gat_fused_b3(FZB g, int ldo) {
    const int dl = blockIdx.x, t = threadIdx.x;
    const int w = t >> 5, lane = t & 31;

    __shared__ int   ssrc[3][CAP];
    __shared__ float se[3][CAP * 3];
    __shared__ float se2[3][CAP];
    __shared__ float red[4][18];
    __shared__ float smv[3][3], ssumv[3][3];
    __shared__ float sm2v[3], ssm2v[3];

    int deg[3];
#pragma unroll
    for (int sl = 0; sl < 3; sl++) {
        int d = g.cnt[sl][dl];
        deg[sl] = d > CAP ? CAP : d;
    }
    const int maxdeg = max(deg[0], max(deg[1], deg[2]));

    // self el/er, all slots (phase B: same x for all slots)
    const float xv = g.x[0][(size_t)dl * DD + t];
    {
        float o[18];
#pragma unroll
        for (int sl = 0; sl < 3; sl++) {
            const float* wl = g.wlr[sl] + (size_t)t * 8;
#pragma unroll
            for (int i = 0; i < 6; i++) o[sl * 6 + i] = xv * wl[i];
        }
#pragma unroll
        for (int off = 16; off; off >>= 1)
#pragma unroll
            for (int i = 0; i < 18; i++) o[i] += __shfl_xor_sync(0xffffffffu, o[i], off);
        if (lane == 0)
#pragma unroll
            for (int i = 0; i < 18; i++) red[w][i] = o[i];
    }
    __syncthreads();
    float elS[3][3], erS[3][3];
#pragma unroll
    for (int sl = 0; sl < 3; sl++)
#pragma unroll
        for (int h = 0; h < 3; h++) {
            elS[sl][h] = red[0][sl*6+h] + red[1][sl*6+h] + red[2][sl*6+h] + red[3][sl*6+h];
            erS[sl][h] = red[0][sl*6+3+h] + red[1][sl*6+3+h] + red[2][sl*6+3+h] + red[3][sl*6+3+h];
        }

    // edge scores + zero padding to CAP
    if (t < CAP) {
#pragma unroll
        for (int sl = 0; sl < 3; sl++) {
            if (t < deg[sl]) {
                int s = g.adj[sl][(size_t)dl * CAP + t];
                ssrc[sl][t] = s;
                float e[3];
                if (s < EXER_N) {
                    const float* el = g.elE[sl] + (size_t)s * 4;
#pragma unroll
                    for (int h = 0; h < 3; h++) e[h] = el[h] + erS[sl][h];
                } else {
#pragma unroll
                    for (int h = 0; h < 3; h++) e[h] = elS[sl][h] + erS[sl][h];
                }
#pragma unroll
                for (int h = 0; h < 3; h++)
                    se[sl][t * 3 + h] = e[h] > 0.f ? e[h] : 0.2f * e[h];
            } else {
                ssrc[sl][t] = 0;
#pragma unroll
                for (int h = 0; h < 3; h++) se[sl][t * 3 + h] = 0.f;
            }
        }
    }
    __syncthreads();

    // softmax1: warp w handles head w, loops slots (3 independent chains)
    if (w < 3) {
#pragma unroll
        for (int sl = 0; sl < 3; sl++) {
            float m = -3.0e38f;
            for (int j = lane; j < deg[sl]; j += 32) m = fmaxf(m, se[sl][j * 3 + w]);
#pragma unroll
            for (int off = 16; off; off >>= 1) m = fmaxf(m, __shfl_xor_sync(0xffffffffu, m, off));
            float s = 0.f;
            for (int j = lane; j < deg[sl]; j += 32) s += expf(se[sl][j * 3 + w] - m);
#pragma unroll
            for (int off = 16; off; off >>= 1) s += __shfl_xor_sync(0xffffffffu, s, off);
            if (lane == 0) { smv[sl][w] = m; ssumv[sl][w] = s; }
        }
    }
    __syncthreads();
#pragma unroll
    for (int sl = 0; sl < 3; sl++)
        if (t < deg[sl]) {
#pragma unroll
            for (int h = 0; h < 3; h++)
                se[sl][t * 3 + h] = expf(se[sl][t * 3 + h] - smv[sl][h]) / ssumv[sl][h];
        }
    __syncthreads();

    // z gather: interleaved across slots (9 loads in flight)
    float sv[3][3];
#pragma unroll
    for (int sl = 0; sl < 3; sl++) {
        const float* r = g.zS3[sl] + (size_t)dl * HD;
        sv[sl][0] = r[t]; sv[sl][1] = r[DD + t]; sv[sl][2] = r[2 * DD + t];
    }
    float acc[3] = {0.f, 0.f, 0.f};
    for (int j = 0; j < maxdeg; j++) {
#pragma unroll
        for (int sl = 0; sl < 3; sl++) {
            int s = ssrc[sl][j];
            float w0 = se[sl][j * 3 + 0], w1 = se[sl][j * 3 + 1], w2 = se[sl][j * 3 + 2];
            float v0, v1, v2;
            if (s < EXER_N) {
                const __nv_bfloat16* b = g.zE3[sl] + (size_t)s * HD;
                v0 = __bfloat162float(b[t]);
                v1 = __bfloat162float(b[DD + t]);
                v2 = __bfloat162float(b[2 * DD + t]);
            } else { v0 = sv[sl][0]; v1 = sv[sl][1]; v2 = sv[sl][2]; }
            acc[sl] += w0 * v0 + w1 * v1 + w2 * v2;
        }
    }
    float zval[3];
#pragma unroll
    for (int sl = 0; sl < 3; sl++) zval[sl] = acc[sl] + g.bz[sl][t];

    // zl/zr self (6 reductions)
    {
        float o[6];
#pragma unroll
        for (int sl = 0; sl < 3; sl++) {
            const float* aw = g.aW[sl];
            o[sl * 2 + 0] = zval[sl] * aw[t];
            o[sl * 2 + 1] = zval[sl] * aw[DD + t];
        }
#pragma unroll
        for (int off = 16; off; off >>= 1)
#pragma unroll
            for (int i = 0; i < 6; i++) o[i] += __shfl_xor_sync(0xffffffffu, o[i], off);
        __syncthreads();
        if (lane == 0)
#pragma unroll
            for (int i = 0; i < 6; i++) red[w][i] = o[i];
    }
    __syncthreads();
    float zlS[3], zrS[3];
#pragma unroll
    for (int sl = 0; sl < 3; sl++) {
        zlS[sl] = red[0][sl*2] + red[1][sl*2] + red[2][sl*2] + red[3][sl*2];
        zrS[sl] = red[0][sl*2+1] + red[1][sl*2+1] + red[2][sl*2+1] + red[3][sl*2+1];
    }

    // attn2 scores + padding
    if (t < CAP) {
#pragma unroll
        for (int sl = 0; sl < 3; sl++) {
            if (t < deg[sl]) {
                int s = ssrc[sl][t];
                float zl = (s < EXER_N) ? g.zlE[sl][s] : zlS[sl];
                se2[sl][t] = zl + zrS[sl];
            } else se2[sl][t] = 0.f;
        }
    }
    __syncthreads();
    if (w < 3) {            // warp w handles slot w
        const int sl = w;
        float m = -3.0e38f;
        for (int j = lane; j < deg[sl]; j += 32) m = fmaxf(m, se2[sl][j]);
#pragma unroll
        for (int off = 16; off; off >>= 1) m = fmaxf(m, __shfl_xor_sync(0xffffffffu, m, off));
        float s = 0.f;
        for (int j = lane; j < deg[sl]; j += 32) s += expf(se2[sl][j] - m);
#pragma unroll
        for (int off = 16; off; off >>= 1) s += __shfl_xor_sync(0xffffffffu, s, off);
        if (lane == 0) { sm2v[sl] = m; ssm2v[sl] = s; }
    }
    __syncthreads();
#pragma unroll
    for (int sl = 0; sl < 3; sl++)
        if (t < deg[sl]) se2[sl][t] = expf(se2[sl][t] - sm2v[sl]) / ssm2v[sl];
    __syncthreads();

    // output gather (interleaved)
    float acc2[3] = {0.f, 0.f, 0.f};
    for (int j = 0; j < maxdeg; j++) {
#pragma unroll
        for (int sl = 0; sl < 3; sl++) {
            int s = ssrc[sl][j];
            float v = (s < EXER_N) ? __bfloat162float(g.zE[sl][(size_t)s * DD + t]) : zval[sl];
            acc2[sl] += se2[sl][j] * v;
        }
    }
#pragma unroll
    for (int sl = 0; sl < 3; sl++) {
        g.out[sl][(size_t)dl * ldo + t] = acc2[sl];
        if (g.out2[sl]) g.out2[sl][(size_t)dl * ldo + t] = acc2[sl];
    }
}

// ---------------- fused GAT, phase D: 2 slots x 2 branches per block ----------
__global__ void gat_fused_m2(FZM g, int ldo) {
    const int dl = blockIdx.x, t = threadIdx.x;
    const int w = t >> 5, lane = t & 31;

    __shared__ int   ssrc[2][CAP];
    __shared__ float seX[2][CAP * 3], seP[2][CAP * 3];
    __shared__ float se2X[2][CAP], se2P[2][CAP];
    __shared__ float red[4][24];
    __shared__ float smv[2][2][3], ssumv[2][2][3];     // [slot][branch][head]
    __shared__ float sm2v[2][2], ssm2v[2][2];

    int deg[2];
#pragma unroll
    for (int sl = 0; sl < 2; sl++) {
        int d = g.cnt[sl][dl];
        deg[sl] = d > CAP ? CAP : d;
    }
    const int maxdeg = max(deg[0], deg[1]);

    // self el/er for 2 slots x 2 branches
    const float xvX = g.xX[0][(size_t)dl * DD + t];
    const float xvP = g.xP[0][(size_t)dl * DD + t];
    {
        float o[24];
#pragma unroll
        for (int sl = 0; sl < 2; sl++) {
            const float* wl = g.wlr[sl] + (size_t)t * 8;
#pragma unroll
            for (int i = 0; i < 6; i++) {
                o[sl * 12 + i]     = xvX * wl[i];
                o[sl * 12 + 6 + i] = xvP * wl[i];
            }
        }
#pragma unroll
        for (int off = 16; off; off >>= 1)
#pragma unroll
            for (int i = 0; i < 24; i++) o[i] += __shfl_xor_sync(0xffffffffu, o[i], off);
        if (lane == 0)
#pragma unroll
            for (int i = 0; i < 24; i++) red[w][i] = o[i];
    }
    __syncthreads();
    float elX[2][3], erX[2][3], elP[2][3], erP[2][3];
#pragma unroll
    for (int sl = 0; sl < 2; sl++)
#pragma unroll
        for (int h = 0; h < 3; h++) {
            elX[sl][h] = red[0][sl*12+h]+red[1][sl*12+h]+red[2][sl*12+h]+red[3][sl*12+h];
            erX[sl][h] = red[0][sl*12+3+h]+red[1][sl*12+3+h]+red[2][sl*12+3+h]+red[3][sl*12+3+h];
            elP[sl][h] = red[0][sl*12+6+h]+red[1][sl*12+6+h]+red[2][sl*12+6+h]+red[3][sl*12+6+h];
            erP[sl][h] = red[0][sl*12+9+h]+red[1][sl*12+9+h]+red[2][sl*12+9+h]+red[3][sl*12+9+h];
        }

    // edge scores + padding
    if (t < CAP) {
#pragma unroll
        for (int sl = 0; sl < 2; sl++) {
            if (t < deg[sl]) {
                int s = g.adj[sl][(size_t)dl * CAP + t];
                ssrc[sl][t] = s;
                float ex[3], ep[3];
                if (s < EXER_N) {
                    const float* el = g.elE[sl] + (size_t)s * 4;
#pragma unroll
                    for (int h = 0; h < 3; h++) { ex[h] = el[h] + erX[sl][h]; ep[h] = el[h] + erP[sl][h]; }
                } else {
#pragma unroll
                    for (int h = 0; h < 3; h++) { ex[h] = elX[sl][h] + erX[sl][h]; ep[h] = elP[sl][h] + erP[sl][h]; }
                }
#pragma unroll
                for (int h = 0; h < 3; h++) {
                    seX[sl][t * 3 + h] = ex[h] > 0.f ? ex[h] : 0.2f * ex[h];
                    seP[sl][t * 3 + h] = ep[h] > 0.f ? ep[h] : 0.2f * ep[h];
                }
            } else {
                ssrc[sl][t] = 0;
#pragma unroll
                for (int h = 0; h < 3; h++) { seX[sl][t * 3 + h] = 0.f; seP[sl][t * 3 + h] = 0.f; }
            }
        }
    }
    __syncthreads();

    // softmax1: warp w = head w; loops slot x branch (4 chains)
    if (w < 3) {
#pragma unroll
        for (int sl = 0; sl < 2; sl++) {
            float mX = -3.0e38f, mP = -3.0e38f;
            for (int j = lane; j < deg[sl]; j += 32) {
                mX = fmaxf(mX, seX[sl][j * 3 + w]);
                mP = fmaxf(mP, seP[sl][j * 3 + w]);
            }
#pragma unroll
            for (int off = 16; off; off >>= 1) {
                mX = fmaxf(mX, __shfl_xor_sync(0xffffffffu, mX, off));
                mP = fmaxf(mP, __shfl_xor_sync(0xffffffffu, mP, off));
            }
            float sX = 0.f, sP = 0.f;
            for (int j = lane; j < deg[sl]; j += 32) {
                sX += expf(seX[sl][j * 3 + w] - mX);
                sP += expf(seP[sl][j * 3 + w] - mP);
            }
#pragma unroll
            for (int off = 16; off; off >>= 1) {
                sX += __shfl_xor_sync(0xffffffffu, sX, off);
                sP += __shfl_xor_sync(0xffffffffu, sP, off);
            }
            if (lane == 0) {
                smv[sl][0][w] = mX; ssumv[sl][0][w] = sX;
                smv[sl][1][w] = mP; ssumv[sl][1][w] = sP;
            }
        }
    }
    __syncthreads();
#pragma unroll
    for (int sl = 0; sl < 2; sl++)
        if (t < deg[sl]) {
#pragma unroll
            for (int h = 0; h < 3; h++) {
                seX[sl][t * 3 + h] = expf(seX[sl][t * 3 + h] - smv[sl][0][h]) / ssumv[sl][0][h];
                seP[sl][t * 3 + h] = expf(seP[sl][t * 3 + h] - smv[sl][1][h]) / ssumv[sl][1][h];
            }
        }
    __syncthreads();

    // z gather (shared exer rows; 2 slots x 2 branches accumulated)
    float svX[2][3], svP[2][3];
#pragma unroll
    for (int sl = 0; sl < 2; sl++) {
        const float* rx = g.zS3X[sl] + (size_t)dl * HD;
        const float* rp = g.zS3P[sl] + (size_t)dl * HD;
        svX[sl][0] = rx[t]; svX[sl][1] = rx[DD + t]; svX[sl][2] = rx[2 * DD + t];
        svP[sl][0] = rp[t]; svP[sl][1] = rp[DD + t]; svP[sl][2] = rp[2 * DD + t];
    }
    float accX[2] = {0.f, 0.f}, accP[2] = {0.f, 0.f};
    for (int j = 0; j < maxdeg; j++) {
#pragma unroll
        for (int sl = 0; sl < 2; sl++) {
            int s = ssrc[sl][j];
            float wx0 = seX[sl][j*3+0], wx1 = seX[sl][j*3+1], wx2 = seX[sl][j*3+2];
            float wp0 = seP[sl][j*3+0], wp1 = seP[sl][j*3+1], wp2 = seP[sl][j*3+2];
            if (s < EXER_N) {
                const __nv_bfloat16* b = g.zE3[sl] + (size_t)s * HD;
                float v0 = __bfloat162float(b[t]);
                float v1 = __bfloat162float(b[DD + t]);
                float v2 = __bfloat162float(b[2 * DD + t]);
                accX[sl] += wx0 * v0 + wx1 * v1 + wx2 * v2;
                accP[sl] += wp0 * v0 + wp1 * v1 + wp2 * v2;
            } else {
                accX[sl] += wx0 * svX[sl][0] + wx1 * svX[sl][1] + wx2 * svX[sl][2];
                accP[sl] += wp0 * svP[sl][0] + wp1 * svP[sl][1] + wp2 * svP[sl][2];
            }
        }
    }
    float zvX[2], zvP[2];
#pragma unroll
    for (int sl = 0; sl < 2; sl++) {
        const float b = g.bz[sl][t];
        zvX[sl] = accX[sl] + b;
        zvP[sl] = accP[sl] + b;
    }

    // zl/zr self (8 reductions)
    {
        float o[8];
#pragma unroll
        for (int sl = 0; sl < 2; sl++) {
            const float* aw = g.aW[sl];
            o[sl*4+0] = zvX[sl] * aw[t];
            o[sl*4+1] = zvX[sl] * aw[DD + t];
            o[sl*4+2] = zvP[sl] * aw[t];
            o[sl*4+3] = zvP[sl] * aw[DD + t];
        }
#pragma unroll
        for (int off = 16; off; off >>= 1)
#pragma unroll
            for (int i = 0; i < 8; i++) o[i] += __shfl_xor_sync(0xffffffffu, o[i], off);
        __syncthreads();
        if (lane == 0)
#pragma unroll
            for (int i = 0; i < 8; i++) red[w][i] = o[i];
    }
    __syncthreads();
    float zlX[2], zrX[2], zlP[2], zrP[2];
#pragma unroll
    for (int sl = 0; sl < 2; sl++) {
        zlX[sl] = red[0][sl*4+0]+red[1][sl*4+0]+red[2][sl*4+0]+red[3][sl*4+0];
        zrX[sl] = red[0][sl*4+1]+red[1][sl*4+1]+red[2][sl*4+1]+red[3][sl*4+1];
        zlP[sl] = red[0][sl*4+2]+red[1][sl*4+2]+red[2][sl*4+2]+red[3][sl*4+2];
        zrP[sl] = red[0][sl*4+3]+red[1][sl*4+3]+red[2][sl*4+3]+red[3][sl*4+3];
    }

    // attn2 scores + padding
    if (t < CAP) {
#pragma unroll
        for (int sl = 0; sl < 2; sl++) {
            if (t < deg[sl]) {
                int s = ssrc[sl][t];
                if (s < EXER_N) {
                    float zl = g.zlE[sl][s];
                    se2X[sl][t] = zl + zrX[sl];
                    se2P[sl][t] = zl + zrP[sl];
                } else {
                    se2X[sl][t] = zlX[sl] + zrX[sl];
                    se2P[sl][t] = zlP[sl] + zrP[sl];
                }
            } else { se2X[sl][t] = 0.f; se2P[sl][t] = 0.f; }
        }
    }
    __syncthreads();
    if (w < 4) {            // warp w -> (slot, branch)
        const int sl = w >> 1, br = w & 1;
        const float* se2 = (br == 0) ? se2X[sl] : se2P[sl];
        float m = -3.0e38f;
        for (int j = lane; j < deg[sl]; j += 32) m = fmaxf(m, se2[j]);
#pragma unroll
        for (int off = 16; off; off >>= 1) m = fmaxf(m, __shfl_xor_sync(0xffffffffu, m, off));
        float s = 0.f;
        for (int j = lane; j < deg[sl]; j += 32) s += expf(se2[j] - m);
#pragma unroll
        for (int off = 16; off; off >>= 1) s += __shfl_xor_sync(0xffffffffu, s, off);
        if (lane == 0) { sm2v[sl][br] = m; ssm2v[sl][br] = s; }
    }
    __syncthreads();
#pragma unroll
    for (int sl = 0; sl < 2; sl++)
        if (t < deg[sl]) {
            se2X[sl][t] = expf(se2X[sl][t] - sm2v[sl][0]) / ssm2v[sl][0];
            se2P[sl][t] = expf(se2P[sl][t] - sm2v[sl][1]) / ssm2v[sl][1];
        }
    __syncthreads();

    // output gather (shared exer rows)
    float acc2X[2] = {0.f, 0.f}, acc2P[2] = {0.f, 0.f};
    for (int j = 0; j < maxdeg; j++) {
#pragma unroll
        for (int sl = 0; sl < 2; sl++) {
            int s = ssrc[sl][j];
            if (s < EXER_N) {
                float v = __bfloat162float(g.zE[sl][(size_t)s * DD + t]);
                acc2X[sl] += se2X[sl][j] * v;
                acc2P[sl] += se2P[sl][j] * v;
            } else {
                acc2X[sl] += se2X[sl][j] * zvX[sl];
                acc2P[sl] += se2P[sl][j] * zvP[sl];
            }
        }
    }
#pragma unroll
    for (int sl = 0; sl < 2; sl++) {
        g.outX[sl][(size_t)dl * ldo + t] = acc2X[sl];
        g.outP[sl][(size_t)dl * ldo + t] = acc2P[sl];
    }
}

// SSL ------------------------------------------------------------------------
__global__ void norm_rows_b(NRB g, const int* __restrict__ ids) {
    int z = blockIdx.y;
    int i = blockIdx.x, t = threadIdx.x;
    int r = ids[i];
    float v = g.emb[z][(size_t)r * DD + t];
    float sq = v * v;
#pragma unroll
    for (int off = 16; off; off >>= 1) sq += __shfl_xor_sync(0xffffffffu, sq, off);
    __shared__ float w4[4];
    if ((t & 31) == 0) w4[t >> 5] = sq;
    __syncthreads();
    float tot = w4[0] + w4[1] + w4[2] + w4[3];
    float nrm = sqrtf(tot);
    g.out[z][(size_t)i * DD + t] = v / fmaxf(nrm, 1e-12f);
}

__global__ void colsum_part(const float* __restrict__ nbp, float* __restrict__ part) {
    int b = blockIdx.x, t = threadIdx.x;
    float s = 0.f;
    const int i0 = b * (BATCH / 16);
#pragma unroll 4
    for (int i = i0; i < i0 + BATCH / 16; i++) s += nbp[(size_t)i * DD + t];
    part[b * DD + t] = s;
}
__global__ void colsum_fin(const float* __restrict__ part, float* __restrict__ S) {
    int t = threadIdx.x;
    float s = 0.f;
#pragma unroll
    for (int b = 0; b < 16; b++) s += part[b * DD + t];
    S[t] = s;
}

__global__ void loss_part(const float* __restrict__ nb, const float* __restrict__ nbp,
                          const float* __restrict__ S, float* __restrict__ lp) {
    const int w = threadIdx.x >> 5, lane = threadIdx.x & 31;
    const int i = blockIdx.x * 8 + w;
    const float4 xv = *(const float4*)(nb  + (size_t)i * DD + lane * 4);
    const float4 yv = *(const float4*)(nbp + (size_t)i * DD + lane * 4);
    const float4 sv = *(const float4*)(S + lane * 4);
    float dg = xv.x * yv.x + xv.y * yv.y + xv.z * yv.z + xv.w * yv.w;
    float rs = xv.x * sv.x + xv.y * sv.y + xv.z * sv.z + xv.w * sv.w;
#pragma unroll
    for (int off = 16; off; off >>= 1) {
        dg += __shfl_xor_sync(0xffffffffu, dg, off);
        rs += __shfl_xor_sync(0xffffffffu, rs, off);
    }
    if (lane == 0) {
        float divided = expf(dg * 5.0f) / (rs * 5.0f + 1e-8f);
        lp[i] = -logf(fmaxf(divided, 1e-8f));
    }
}
__global__ void loss_fin(const float* __restrict__ lp, float* __restrict__ out) {
    int t = threadIdx.x;
    float s = 0.f;
#pragma unroll
    for (int k = 0; k < BATCH / 256; k++) s += lp[t + k * 256];
    __shared__ float red[256];
    red[t] = s;
    __syncthreads();
    for (int st = 128; st; st >>= 1) { if (t < st) red[t] += red[t + st]; __syncthreads(); }
    if (t == 0) out[0] = red[0];
}

// ---------------- host orchestration ------------------------------------------
extern "C" void kernel_launch(void* const* d_in, const int* in_sizes, int n_in,
                              void* d_out_, int out_size)
{
    const float* stu_table  = (const float*)d_in[0];
    const float* exer_table = (const float*)d_in[1];
    const float* gat_W  = (const float*)d_in[2];
    const float* attn_l = (const float*)d_in[3];
    const float* attn_r = (const float*)d_in[4];
    const float* gat_b  = (const float*)d_in[5];
    const float* fc_W   = (const float*)d_in[6];
    const float* fc_b   = (const float*)d_in[7];
    const float* aW     = (const float*)d_in[8];
    const float* f1W    = (const float*)d_in[9];
    const float* f1b    = (const float*)d_in[10];
    const float* f2W    = (const float*)d_in[11];
    const float* f2b    = (const float*)d_in[12];
    const int* e_src[3] = {(const int*)d_in[13], (const int*)d_in[15], (const int*)d_in[21]};
    const int* e_dst[3] = {(const int*)d_in[14], (const int*)d_in[16], (const int*)d_in[22]};
    int e_n[3] = {in_sizes[13], in_sizes[15], in_sizes[21]};
    const int* stu_id = (const int*)d_in[23];
    float* d_out = (float*)d_out_;
    (void)n_in;

    float* FA = nullptr; int* IA = nullptr; __nv_bfloat16* HA = nullptr;
    cudaGetSymbolAddress((void**)&FA, g_farena);
    cudaGetSymbolAddress((void**)&IA, g_iarena);
    cudaGetSymbolAddress((void**)&HA, g_harena);

    float* Wz3   = FA + O_Wz3;
    float* Wzc   = FA + O_Wzc;
    float* Wlr   = FA + O_Wlr;
    float* bz    = FA + O_bz;
    float* zE    = FA + O_zE;
    float* elE   = FA + O_elE;
    float* zlE   = FA + O_zlE;
    float* erD   = FA + O_erD;
    float* zrD   = FA + O_zrD;
    float* ABCD  = FA + O_ABCD;
    float* ABPCD = FA + O_ABPCD;
    float* stu1  = FA + O_stu1;
    float* stu1p = FA + O_stu1p;
    float* XYX   = FA + O_XYX;
    float* XYP   = FA + O_XYP;
    float* stu2  = FA + O_stu2;
    float* stu2p = FA + O_stu2p;
    float* nb    = FA + O_nb;
    float* nbp   = FA + O_nbp;
    float* Sv    = FA + O_S;
    float* lossD = FA + O_lossd;
    float* partV = FA + O_part;
    float* lpart = FA + O_lpart;
    __nv_bfloat16* zE3h = HA + OH_zE3;
    __nv_bfloat16* zEh  = HA + OH_zE;

    const int pidx[3] = {0, 1, 4};
    const int gM_E = (EXER_N + 127) / 128;
    const int gM_S = (STU_N + 127) / 128;

    auto scr  = [&](int sc, size_t off) { return FA + O_SCR + (size_t)sc * SC_TOT + off; };
    auto adjP = [&](int s) { return IA + OI_adj + (size_t)s * STU_N * CAP; };
    auto cntP = [&](int s) { return IA + OI_cnt + (size_t)s * STU_N; };

    // ---- weight precompute + adjacency ----
    wz_kernel<<<dim3(DD, 5), DD>>>(gat_W, fc_W, Wz3, Wzc);
    wlr_kernel<<<5, DD>>>(gat_W, attn_l, attn_r, Wlr);
    bz_kernel<<<5, DD>>>(gat_b, fc_W, fc_b, bz);
    zero_int<<<(3 * STU_N + 255) / 256, 256>>>(IA + OI_cnt, 3 * STU_N);
    {
        ADJB g{};
        int max_e = 0;
        for (int s = 0; s < 3; s++) {
            g.src[s] = e_src[s]; g.dst[s] = e_dst[s]; g.ecnt[s] = e_n[s];
            g.adj[s] = adjP(s);  g.cnt[s] = cntP(s);
            if (e_n[s] > max_e) max_e = e_n[s];
        }
        build_adj_b<<<dim3((max_e + 255) / 256, 3), 256>>>(g);
    }

    // ---- phase A: exer-side invariants ----
    {
        GB g{};
        for (int s = 0; s < 3; s++) {
            g.A[s] = exer_table;
            g.B[s] = Wz3 + (size_t)pidx[s] * DD * HD;
            g.Ch[s] = zE3h + (size_t)s * EXER_N * HD;
        }
        tgemm_b<<<dim3(HD / 128, gM_E, 3), 256>>>(g, DD, HD, 0, EXER_N, HD, DD);
    }
    {
        GB g{};
        for (int s = 0; s < 3; s++) {
            g.A[s] = exer_table;
            g.B[s] = Wzc + (size_t)pidx[s] * DD * DD;
            g.C[s] = zE + (size_t)s * EXER_N * DD;
            g.Ch[s] = zEh + (size_t)s * EXER_N * DD;
            g.bias[s] = bz + (size_t)pidx[s] * DD;
        }
        tgemm_b<<<dim3(1, gM_E, 3), 256>>>(g, DD, DD, 0, EXER_N, DD, DD);
    }
    {
        ESB g{};
        for (int s = 0; s < 3; s++) {
            g.x[s]   = exer_table;
            g.wlr[s] = Wlr + (size_t)pidx[s] * DD * 8;
            g.el[s]  = elE + (size_t)s * EXER_N * 4;
            g.er[s]  = erD;
        }
        escore_b<<<dim3(EXER_N, 3), 128>>>(g);
    }
    {
        ZZB g{};
        for (int s = 0; s < 3; s++) {
            g.z[s]  = zE + (size_t)s * EXER_N * DD;
            g.aW[s] = aW + (size_t)pidx[s] * 2 * DD;
            g.zl[s] = zlE + (size_t)s * EXER_N;
            g.zr[s] = zrD;
        }
        zlzr_b<<<dim3(EXER_N, 3), 128>>>(g);
    }

    // ---- layers 2,3: single GEMM, dual-store ----
    {
        GB g{};
        for (int i = 0; i < 2; i++) {
            int coff = (i == 0) ? 2 * DD : 3 * DD;
            g.A[i] = stu_table;
            g.B[i] = Wzc + (size_t)(2 + i) * DD * DD;
            g.C[i] = ABCD + coff;
            g.C2[i] = ABPCD + coff;
            g.bias[i] = bz + (size_t)(2 + i) * DD;
        }
        tgemm_b<<<dim3(1, gM_S, 2), 256>>>(g, DD, 4 * DD, 0, STU_N, DD, DD);
    }

    // ---- phase B: zS3 GEMM + ONE slot-merged fused GAT launch ----
    {
        const int slot[3] = {0, 1, 2};
        {
            GB g{};
            for (int i = 0; i < 3; i++) {
                g.A[i] = stu_table;
                g.B[i] = Wz3 + (size_t)pidx[slot[i]] * DD * HD;
                g.C[i] = scr(i, SC_zS3);
            }
            tgemm_b<<<dim3(HD / 128, gM_S, 3), 256>>>(g, DD, HD, 0, STU_N, HD, DD);
        }
        {
            FZB g{};
            float* outb[3]  = {ABCD, ABCD + DD, ABPCD + DD};
            float* outb2[3] = {ABPCD, nullptr, nullptr};
            for (int i = 0; i < 3; i++) {
                int s = slot[i];
                g.adj[i] = adjP(s); g.cnt[i] = cntP(s);
                g.x[i]   = stu_table;
                g.wlr[i] = Wlr + (size_t)pidx[s] * DD * 8;
                g.elE[i] = elE + (size_t)s * EXER_N * 4;
                g.zE3[i] = zE3h + (size_t)s * EXER_N * HD;
                g.zS3[i] = scr(i, SC_zS3);
                g.zE[i]  = zEh + (size_t)s * EXER_N * DD;
                g.zlE[i] = zlE + (size_t)s * EXER_N;
                g.bz[i]  = bz + (size_t)pidx[s] * DD;
                g.aW[i]  = aW + (size_t)pidx[s] * 2 * DD;
                g.out[i]  = outb[i];
                g.out2[i] = outb2[i];
            }
            gat_fused_b3<<<STU_N, 128>>>(g, 4 * DD);
        }
    }

    // ---- fuse1: K=512 GEMM + residual ----
    {
        GB g{};
        g.A[0] = ABCD;  g.C[0] = stu1;  g.bias[0] = f1b; g.addm[0] = stu_table;
        g.A[1] = ABPCD; g.C[1] = stu1p; g.bias[1] = f1b; g.addm[1] = stu_table;
        g.B[0] = f1W; g.B[1] = f1W;
        tgemm_b<<<dim3(1, gM_S, 2), 256>>>(g, 4 * DD, DD, DD, STU_N, DD, 4 * DD);
    }

    // ---- phase D: zS3 GEMM (z=4) + ONE slot+branch-merged fused GAT ----
    {
        const float* xS[4] = {stu1, stu1, stu1p, stu1p};
        const int slot4[4] = {0, 1, 0, 1};
        {
            GB g{};
            for (int i = 0; i < 4; i++) {
                g.A[i] = xS[i];
                g.B[i] = Wz3 + (size_t)pidx[slot4[i]] * DD * HD;
                g.C[i] = scr(i, SC_zS3);
            }
            tgemm_b<<<dim3(HD / 128, gM_S, 4), 256>>>(g, DD, HD, 0, STU_N, HD, DD);
        }
        {
            FZM g{};
            for (int s = 0; s < 2; s++) {
                g.adj[s] = adjP(s); g.cnt[s] = cntP(s);
                g.wlr[s] = Wlr + (size_t)pidx[s] * DD * 8;
                g.elE[s] = elE + (size_t)s * EXER_N * 4;
                g.zE3[s] = zE3h + (size_t)s * EXER_N * HD;
                g.zE[s]  = zEh + (size_t)s * EXER_N * DD;
                g.zlE[s] = zlE + (size_t)s * EXER_N;
                g.bz[s]  = bz + (size_t)pidx[s] * DD;
                g.aW[s]  = aW + (size_t)pidx[s] * 2 * DD;
                g.xX[s]  = stu1;  g.xP[s] = stu1p;
                g.zS3X[s] = scr(s, SC_zS3);
                g.zS3P[s] = scr(s + 2, SC_zS3);
                g.outX[s] = XYX + (size_t)s * DD;
                g.outP[s] = XYP + (size_t)s * DD;
            }
            gat_fused_m2<<<STU_N, 128>>>(g, 2 * DD);
        }
    }

    // ---- fusion2: K=256 + residual; stu2 dual-stored to d_out ----
    const int NOUT = STU_N * DD;
    {
        GB g{};
        g.A[0] = XYX; g.C[0] = stu2;  g.bias[0] = f2b; g.addm[0] = stu1;
        g.A[1] = XYP; g.C[1] = stu2p; g.bias[1] = f2b; g.addm[1] = stu1p;
        g.B[0] = f2W; g.B[1] = f2W;
        if (out_size >= NOUT) g.C2[0] = d_out;
        tgemm_b<<<dim3(1, gM_S, 2), 256>>>(g, 2 * DD, DD, DD, STU_N, DD, 2 * DD);
    }

    float* lossdst = lossD;
    if (out_size == 1) lossdst = d_out;
    else if (out_size > NOUT) lossdst = d_out + (out_size - 1);

    {
        NRB g{};
        g.emb[0] = stu2;  g.out[0] = nb;
        g.emb[1] = stu2p; g.out[1] = nbp;
        norm_rows_b<<<dim3(BATCH, 2), 128>>>(g, stu_id);
    }
    colsum_part<<<16, 128>>>(nbp, partV);
    colsum_fin<<<1, 128>>>(partV, Sv);
    loss_part<<<BATCH / 8, 256>>>(nb, nbp, Sv, lpart);
    loss_fin<<<1, 256>>>(lpart, lossdst);
}

// round 16
// speedup vs baseline: 1.2883x; 1.2883x over previous
#include <cuda_runtime.h>
#include <cuda_bf16.h>
#include <math.h>
#include <stdint.h>

#define EXER_N 10000
#define STU_N  20000
#define DD     128
#define HH     3
#define HD     384
#define CAP    96
#define BATCH  2048

#define SZF(x) ((size_t)(x))

// ---------------- scratch arena ---------------------------------------------
static constexpr size_t O_Wz3   = 0;
static constexpr size_t O_Wzc   = O_Wz3   + SZF(5)*DD*HD;
static constexpr size_t O_Wlr   = O_Wzc   + SZF(5)*DD*DD;
static constexpr size_t O_bz    = O_Wlr   + SZF(5)*DD*8;
static constexpr size_t O_zE    = O_bz    + SZF(5)*DD;
static constexpr size_t O_elE   = O_zE    + SZF(3)*EXER_N*DD;
static constexpr size_t O_zlE   = O_elE   + SZF(3)*EXER_N*4;
static constexpr size_t O_erD   = O_zlE   + SZF(3)*EXER_N;
static constexpr size_t O_zrD   = O_erD   + SZF(EXER_N)*4;
static constexpr size_t O_ABCD  = O_zrD   + SZF(EXER_N);
static constexpr size_t O_ABPCD = O_ABCD  + SZF(STU_N)*4*DD;
static constexpr size_t O_stu1  = O_ABPCD + SZF(STU_N)*4*DD;
static constexpr size_t O_stu1p = O_stu1  + SZF(STU_N)*DD;
static constexpr size_t O_XYX   = O_stu1p + SZF(STU_N)*DD;
static constexpr size_t O_XYP   = O_XYX   + SZF(STU_N)*2*DD;
static constexpr size_t O_stu2  = O_XYP   + SZF(STU_N)*2*DD;
static constexpr size_t O_stu2p = O_stu2  + SZF(STU_N)*DD;
static constexpr size_t O_nb    = O_stu2p + SZF(STU_N)*DD;
static constexpr size_t O_nbp   = O_nb    + SZF(BATCH)*DD;
static constexpr size_t O_S     = O_nbp   + SZF(BATCH)*DD;
static constexpr size_t O_lossd = O_S     + DD;
static constexpr size_t O_part  = O_lossd + 16;
static constexpr size_t O_lpart = O_part  + SZF(16)*DD;
static constexpr size_t O_SCR   = O_lpart + BATCH;
static constexpr size_t SC_zS3  = 0;
static constexpr size_t SC_TOT  = SC_zS3 + SZF(STU_N)*HD;
static constexpr size_t F_TOT   = O_SCR + 4*SC_TOT;

static constexpr size_t OH_zE3  = 0;
static constexpr size_t OH_zE   = OH_zE3 + SZF(3)*EXER_N*HD;
static constexpr size_t H_TOT   = OH_zE  + SZF(3)*EXER_N*DD;

static constexpr size_t OI_adj  = 0;
static constexpr size_t OI_cnt  = SZF(3)*STU_N*CAP;
static constexpr size_t I_TOT   = OI_cnt + SZF(3)*STU_N;

__device__ __align__(256) float          g_farena[F_TOT];
__device__ __align__(256) __nv_bfloat16  g_harena[H_TOT];
__device__ __align__(256) int            g_iarena[I_TOT];

// ---------------- batched pointer structs ------------------------------------
struct GB {
    const float*    A[4];
    const float*    B[4];
    float*          C[4];
    float*          C2[4];
    __nv_bfloat16*  Ch[4];
    const float*    bias[4];
    const float*    addm[4];
};
struct EZB {                      // fused exer escore + zlzr
    const float* x[4];
    const float* wlr[4];
    const float* z[4];
    const float* aW[4];
    float*       el[4];
    float*       er[4];
    float*       zl[4];
    float*       zr[4];
};
struct FZB {                      // fully fused GAT (single branch)
    const int*           adj[4];
    const int*           cnt[4];
    const float*         x[4];
    const float*         wlr[4];
    const float*         elE[4];
    const __nv_bfloat16* zE3[4];
    const float*         zS3[4];
    const __nv_bfloat16* zE[4];
    const float*         zlE[4];
    const float*         bz[4];
    const float*         aW[4];
    float*               out[4];
    float*               out2[4];
};
struct FZM {                      // fully fused GAT, merged X/P per slot
    const int*           adj[2];
    const int*           cnt[2];
    const float*         wlr[2];
    const float*         elE[2];
    const __nv_bfloat16* zE3[2];
    const __nv_bfloat16* zE[2];
    const float*         zlE[2];
    const float*         bz[2];
    const float*         aW[2];
    const float*         xX[2];
    const float*         xP[2];
    const float*         zS3X[2];
    const float*         zS3P[2];
    float*               outX[2];
    float*               outP[2];
};
struct ADJB {
    const int* src[3];
    const int* dst[3];
    int        ecnt[3];
    int*       adj[3];
    int*       cnt[3];
};
struct NRB {
    const float* emb[2];
    float*       out[2];
};

// ---------------- TF32 tensor-core batched GEMM (128x128, best config) -------
__device__ __forceinline__ uint32_t f2tf32(float x) {
    uint32_t u;
    asm("cvt.rna.tf32.f32 %0, %1;" : "=r"(u) : "f"(x));
    return u;
}
__device__ __forceinline__ void mma_tf32(float* c, uint32_t a0, uint32_t a1,
                                         uint32_t a2, uint32_t a3,
                                         uint32_t b0, uint32_t b1) {
    asm volatile(
        "mma.sync.aligned.m16n8k8.row.col.f32.tf32.tf32.f32 "
        "{%0,%1,%2,%3}, {%4,%5,%6,%7}, {%8,%9}, {%0,%1,%2,%3};"
        : "+f"(c[0]), "+f"(c[1]), "+f"(c[2]), "+f"(c[3])
        : "r"(a0), "r"(a1), "r"(a2), "r"(a3), "r"(b0), "r"(b1));
}

#define SPAD 136

__global__ __launch_bounds__(256, 2)
void tgemm_b(GB g, int lda, int ldc, int ldadd, int M, int N, int K)
{
    const int z = blockIdx.z;
    const float* __restrict__ A    = g.A[z];
    const float* __restrict__ B    = g.B[z];
    float*                    C    = g.C[z];
    float*                    C2   = g.C2[z];
    __nv_bfloat16*            Ch   = g.Ch[z];
    const float*              bias = g.bias[z];
    const float*              addm = g.addm[z];

    __shared__ uint32_t As[2][16][SPAD];
    __shared__ uint32_t Bs[2][16][SPAD];

    const int tid  = threadIdx.x;
    const int bm   = blockIdx.y * 128;
    const int bn   = blockIdx.x * 128;
    const int lane = tid & 31;
    const int gid  = lane >> 2;
    const int tg   = lane & 3;
    const int warp = tid >> 5;
    const int wm   = warp & 3;
    const int wn   = warp >> 2;

    float acc[2][8][4];
#pragma unroll
    for (int mt = 0; mt < 2; mt++)
#pragma unroll
        for (int nt = 0; nt < 8; nt++)
#pragma unroll
            for (int c = 0; c < 4; c++) acc[mt][nt][c] = 0.f;

    const int am  = tid >> 1;
    const int ak0 = (tid & 1) * 4;
    const int brr = tid >> 5;
    const int bcc = (tid & 31) * 4;

    const bool arow_ok = (bm + am < M);
    float4 av0, av1, bv0, bv1;

    auto ldtile = [&](int k0) {
        av0 = arow_ok ? *(const float4*)(A + (size_t)(bm + am) * lda + k0 + ak0)
                      : make_float4(0.f, 0.f, 0.f, 0.f);
        av1 = arow_ok ? *(const float4*)(A + (size_t)(bm + am) * lda + k0 + 8 + ak0)
                      : make_float4(0.f, 0.f, 0.f, 0.f);
        bv0 = *(const float4*)(B + (size_t)(k0 + brr) * N + bn + bcc);
        bv1 = *(const float4*)(B + (size_t)(k0 + 8 + brr) * N + bn + bcc);
    };
    auto sttile = [&](int p) {
        As[p][ak0 + 0][am] = f2tf32(av0.x);
        As[p][ak0 + 1][am] = f2tf32(av0.y);
        As[p][ak0 + 2][am] = f2tf32(av0.z);
        As[p][ak0 + 3][am] = f2tf32(av0.w);
        As[p][8 + ak0 + 0][am] = f2tf32(av1.x);
        As[p][8 + ak0 + 1][am] = f2tf32(av1.y);
        As[p][8 + ak0 + 2][am] = f2tf32(av1.z);
        As[p][8 + ak0 + 3][am] = f2tf32(av1.w);
        uint4 t0 = make_uint4(f2tf32(bv0.x), f2tf32(bv0.y), f2tf32(bv0.z), f2tf32(bv0.w));
        uint4 t1 = make_uint4(f2tf32(bv1.x), f2tf32(bv1.y), f2tf32(bv1.z), f2tf32(bv1.w));
        *(uint4*)(&Bs[p][brr][bcc]) = t0;
        *(uint4*)(&Bs[p][8 + brr][bcc]) = t1;
    };

    ldtile(0);
    sttile(0);

    const int nt_tiles = K / 16;
    for (int kt = 0; kt < nt_tiles; kt++) {
        const int p = kt & 1;
        const bool more = (kt + 1 < nt_tiles);
        if (more) ldtile((kt + 1) * 16);
        __syncthreads();

#pragma unroll
        for (int ks = 0; ks < 2; ks++) {
            const int kk = ks * 8;
            uint32_t bf[8][2];
#pragma unroll
            for (int nt = 0; nt < 8; nt++) {
                const int n0 = wn * 64 + nt * 8 + gid;
                bf[nt][0] = Bs[p][kk + tg][n0];
                bf[nt][1] = Bs[p][kk + tg + 4][n0];
            }
#pragma unroll
            for (int mt = 0; mt < 2; mt++) {
                const int m0 = wm * 32 + mt * 16;
                uint32_t a0 = As[p][kk + tg][m0 + gid];
                uint32_t a1 = As[p][kk + tg][m0 + gid + 8];
                uint32_t a2 = As[p][kk + tg + 4][m0 + gid];
                uint32_t a3 = As[p][kk + tg + 4][m0 + gid + 8];
#pragma unroll
                for (int nt = 0; nt < 8; nt++)
                    mma_tf32(acc[mt][nt], a0, a1, a2, a3, bf[nt][0], bf[nt][1]);
            }
        }
        if (more) sttile(p ^ 1);
    }

#pragma unroll
    for (int mt = 0; mt < 2; mt++) {
        const int r0 = bm + wm * 32 + mt * 16 + gid;
        const int r1 = r0 + 8;
#pragma unroll
        for (int nt = 0; nt < 8; nt++) {
            const int n = bn + wn * 64 + nt * 8 + tg * 2;
            float2 v0 = make_float2(acc[mt][nt][0], acc[mt][nt][1]);
            float2 v1 = make_float2(acc[mt][nt][2], acc[mt][nt][3]);
            if (bias) {
                float b0 = bias[n], b1 = bias[n + 1];
                v0.x += b0; v0.y += b1;
                v1.x += b0; v1.y += b1;
            }
            if (r0 < M) {
                float2 o = v0;
                if (addm) {
                    const float2 ad = *(const float2*)(addm + (size_t)r0 * ldadd + n);
                    o.x += ad.x; o.y += ad.y;
                }
                if (C)  *(float2*)(C + (size_t)r0 * ldc + n) = o;
                if (C2) *(float2*)(C2 + (size_t)r0 * ldc + n) = o;
                if (Ch) *(__nv_bfloat162*)(Ch + (size_t)r0 * ldc + n) =
                            __floats2bfloat162_rn(o.x, o.y);
            }
            if (r1 < M) {
                float2 o = v1;
                if (addm) {
                    const float2 ad = *(const float2*)(addm + (size_t)r1 * ldadd + n);
                    o.x += ad.x; o.y += ad.y;
                }
                if (C)  *(float2*)(C + (size_t)r1 * ldc + n) = o;
                if (C2) *(float2*)(C2 + (size_t)r1 * ldc + n) = o;
                if (Ch) *(__nv_bfloat162*)(Ch + (size_t)r1 * ldc + n) =
                            __floats2bfloat162_rn(o.x, o.y);
            }
        }
    }
}

// ---------------- weight precompute (exact fp32) -----------------------------
__global__ void wz_kernel(const float* __restrict__ gatW, const float* __restrict__ fcW,
                          float* __restrict__ Wz3, float* __restrict__ Wzc) {
    int p = blockIdx.y;
    int k = blockIdx.x;
    int n = threadIdx.x;
    const float* Wrow = gatW + ((size_t)p * DD + k) * HD;
    const float* F = fcW + (size_t)p * HD * DD;
    __shared__ float wr[HD];
    for (int i = n; i < HD; i += DD) wr[i] = Wrow[i];
    __syncthreads();
    float a0 = 0.f, a1 = 0.f, a2 = 0.f;
    for (int d = 0; d < DD; d++) {
        a0 += wr[d]          * F[(size_t)d * DD + n];
        a1 += wr[DD + d]     * F[(size_t)(DD + d) * DD + n];
        a2 += wr[2 * DD + d] * F[(size_t)(2 * DD + d) * DD + n];
    }
    size_t o = ((size_t)p * DD + k) * HD;
    Wz3[o + n] = a0; Wz3[o + DD + n] = a1; Wz3[o + 2 * DD + n] = a2;
    Wzc[((size_t)p * DD + k) * DD + n] = a0 + a1 + a2;
}

__global__ void wlr_kernel(const float* __restrict__ gatW, const float* __restrict__ al,
                           const float* __restrict__ ar, float* __restrict__ Wlr) {
    int p = blockIdx.x;
    int k = threadIdx.x;
    __shared__ float sal[HD], sar[HD];
    for (int i = k; i < HD; i += DD) {
        sal[i] = al[(size_t)p * HD + i];
        sar[i] = ar[(size_t)p * HD + i];
    }
    __syncthreads();
    const float* Wrow = gatW + ((size_t)p * DD + k) * HD;
    float o[6] = {0.f, 0.f, 0.f, 0.f, 0.f, 0.f};
    for (int h = 0; h < 3; h++)
        for (int d = 0; d < DD; d++) {
            float w = Wrow[h * DD + d];
            o[h]     += w * sal[h * DD + d];
            o[3 + h] += w * sar[h * DD + d];
        }
#pragma unroll
    for (int i = 0; i < 6; i++) Wlr[((size_t)p * DD + k) * 8 + i] = o[i];
}

__global__ void bz_kernel(const float* __restrict__ gb, const float* __restrict__ fcW,
                          const float* __restrict__ fcb, float* __restrict__ bz) {
    int p = blockIdx.x, n = threadIdx.x;
    const float* g = gb + (size_t)p * HD;
    const float* W = fcW + (size_t)p * HD * DD;
    float s = fcb[(size_t)p * DD + n];
    for (int k = 0; k < HD; k++) s += g[k] * W[(size_t)k * DD + n];
    bz[(size_t)p * DD + n] = s;
}

// ---------------- small batched kernels ---------------------------------------
__global__ void zero_int(int* p, int n) {
    int i = blockIdx.x * blockDim.x + threadIdx.x;
    if (i < n) p[i] = 0;
}
__global__ void build_adj_b(ADJB g) {
    int z = blockIdx.y;
    int i = blockIdx.x * blockDim.x + threadIdx.x;
    if (i >= g.ecnt[z]) return;
    int d = g.dst[z][i];
    if (d < EXER_N) return;
    int dl = d - EXER_N;
    int slot = atomicAdd(&g.cnt[z][dl], 1);
    if (slot < CAP) g.adj[z][(size_t)dl * CAP + slot] = g.src[z][i];
}

// fused exer-side escore + zlzr: 8 warp reductions per node
__global__ void ezl_b(EZB g) {
    int z = blockIdx.y;
    int n = blockIdx.x, t = threadIdx.x;
    float xv = g.x[z][(size_t)n * DD + t];
    float zv = g.z[z][(size_t)n * DD + t];
    const float* w = g.wlr[z] + (size_t)t * 8;
    const float* aw = g.aW[z];
    float o[8];
#pragma unroll
    for (int i = 0; i < 6; i++) o[i] = xv * w[i];
    o[6] = zv * aw[t];
    o[7] = zv * aw[DD + t];
#pragma unroll
    for (int off = 16; off; off >>= 1)
#pragma unroll
        for (int i = 0; i < 8; i++) o[i] += __shfl_xor_sync(0xffffffffu, o[i], off);
    __shared__ float red[4][8];
    int wp = t >> 5;
    if ((t & 31) == 0)
#pragma unroll
        for (int i = 0; i < 8; i++) red[wp][i] = o[i];
    __syncthreads();
    if (t < 8) {
        float v = red[0][t] + red[1][t] + red[2][t] + red[3][t];
        if (t < 3)       g.el[z][(size_t)n * 4 + t] = v;
        else if (t < 6)  g.er[z][(size_t)n * 4 + (t - 3)] = v;
        else if (t == 6) g.zl[z][n] = v;
        else             g.zr[z][n] = v;
    }
}

// ---------------- fully fused GAT kernel (single branch) ----------------------
__global__ void gat_fused_b(FZB g, int ldo) {
    const int z = blockIdx.y;
    const int dl = blockIdx.x, t = threadIdx.x;
    int deg = g.cnt[z][dl]; if (deg > CAP) deg = CAP;

    __shared__ int   ssrc[CAP];
    __shared__ float se[CAP * 3];
    __shared__ float se2[CAP];
    __shared__ float red[4][6];
    __shared__ float sm[3], ssum[3];
    __shared__ float sm2, ssm2;

    const int w = t >> 5, lane = t & 31;

    float xv = g.x[z][(size_t)dl * DD + t];
    {
        const float* wl = g.wlr[z] + (size_t)t * 8;
        float o[6];
#pragma unroll
        for (int i = 0; i < 6; i++) o[i] = xv * wl[i];
#pragma unroll
        for (int off = 16; off; off >>= 1)
#pragma unroll
            for (int i = 0; i < 6; i++) o[i] += __shfl_xor_sync(0xffffffffu, o[i], off);
        if (lane == 0)
#pragma unroll
            for (int i = 0; i < 6; i++) red[w][i] = o[i];
    }
    __syncthreads();
    float elS[3], erS[3];
#pragma unroll
    for (int h = 0; h < 3; h++) {
        elS[h] = red[0][h] + red[1][h] + red[2][h] + red[3][h];
        erS[h] = red[0][3 + h] + red[1][3 + h] + red[2][3 + h] + red[3][3 + h];
    }

    if (t < deg) {
        int s = g.adj[z][(size_t)dl * CAP + t];
        ssrc[t] = s;
        float e[3];
        if (s < EXER_N) {
            const float* el = g.elE[z] + (size_t)s * 4;
#pragma unroll
            for (int h = 0; h < 3; h++) e[h] = el[h] + erS[h];
        } else {
#pragma unroll
            for (int h = 0; h < 3; h++) e[h] = elS[h] + erS[h];
        }
#pragma unroll
        for (int h = 0; h < 3; h++)
            se[t * 3 + h] = e[h] > 0.f ? e[h] : 0.2f * e[h];
    }
    __syncthreads();

    if (w < 3) {
        float m = -3.0e38f;
        for (int j = lane; j < deg; j += 32) m = fmaxf(m, se[j * 3 + w]);
#pragma unroll
        for (int off = 16; off; off >>= 1) m = fmaxf(m, __shfl_xor_sync(0xffffffffu, m, off));
        float s = 0.f;
        for (int j = lane; j < deg; j += 32) s += expf(se[j * 3 + w] - m);
#pragma unroll
        for (int off = 16; off; off >>= 1) s += __shfl_xor_sync(0xffffffffu, s, off);
        if (lane == 0) { sm[w] = m; ssum[w] = s; }
    }
    __syncthreads();
    if (t < deg) {
#pragma unroll
        for (int h = 0; h < 3; h++)
            se[t * 3 + h] = expf(se[t * 3 + h] - sm[h]) / ssum[h];
    }
    __syncthreads();

    const __nv_bfloat16* zE3 = g.zE3[z];
    const float* zS3row = g.zS3[z] + (size_t)dl * HD;
    const float sv0 = zS3row[t], sv1 = zS3row[DD + t], sv2 = zS3row[2 * DD + t];
    float acc = 0.f;
    for (int j = 0; j < deg; j++) {
        int s = ssrc[j];
        float v0, v1, v2;
        if (s < EXER_N) {
            const __nv_bfloat16* b = zE3 + (size_t)s * HD;
            v0 = __bfloat162float(b[t]);
            v1 = __bfloat162float(b[DD + t]);
            v2 = __bfloat162float(b[2 * DD + t]);
        } else { v0 = sv0; v1 = sv1; v2 = sv2; }
        acc += se[j * 3 + 0] * v0 + se[j * 3 + 1] * v1 + se[j * 3 + 2] * v2;
    }
    const float zval = acc + g.bz[z][t];

    {
        const float* aw = g.aW[z];
        float a = zval * aw[t];
        float b = zval * aw[DD + t];
#pragma unroll
        for (int off = 16; off; off >>= 1) {
            a += __shfl_xor_sync(0xffffffffu, a, off);
            b += __shfl_xor_sync(0xffffffffu, b, off);
        }
        __syncthreads();
        if (lane == 0) { red[w][0] = a; red[w][1] = b; }
    }
    __syncthreads();
    const float zlS = red[0][0] + red[1][0] + red[2][0] + red[3][0];
    const float zrS = red[0][1] + red[1][1] + red[2][1] + red[3][1];

    if (t < deg) {
        int s = ssrc[t];
        float zl = (s < EXER_N) ? g.zlE[z][s] : zlS;
        se2[t] = zl + zrS;
    }
    __syncthreads();
    if (w == 0) {
        float m = -3.0e38f;
        for (int jj = lane; jj < deg; jj += 32) m = fmaxf(m, se2[jj]);
#pragma unroll
        for (int off = 16; off; off >>= 1) m = fmaxf(m, __shfl_xor_sync(0xffffffffu, m, off));
        float s = 0.f;
        for (int jj = lane; jj < deg; jj += 32) s += expf(se2[jj] - m);
#pragma unroll
        for (int off = 16; off; off >>= 1) s += __shfl_xor_sync(0xffffffffu, s, off);
        if (lane == 0) { sm2 = m; ssm2 = s; }
    }
    __syncthreads();
    if (t < deg) se2[t] = expf(se2[t] - sm2) / ssm2;
    __syncthreads();

    const __nv_bfloat16* zE = g.zE[z];
    float acc2 = 0.f;
    for (int j = 0; j < deg; j++) {
        int s = ssrc[j];
        float v = (s < EXER_N) ? __bfloat162float(zE[(size_t)s * DD + t]) : zval;
        acc2 += se2[j] * v;
    }
    g.out[z][(size_t)dl * ldo + t] = acc2;
    if (g.out2[z]) g.out2[z][(size_t)dl * ldo + t] = acc2;
}

// ---------------- fully fused GAT kernel, merged X/P per slot -----------------
__global__ void gat_fused_m(FZM g, int ldo) {
    const int z = blockIdx.y;
    const int dl = blockIdx.x, t = threadIdx.x;
    int deg = g.cnt[z][dl]; if (deg > CAP) deg = CAP;

    __shared__ int   ssrc[CAP];
    __shared__ float seX[CAP * 3], seP[CAP * 3];
    __shared__ float se2X[CAP], se2P[CAP];
    __shared__ float red[4][12];
    __shared__ float smX[3], ssumX[3], smP[3], ssumP[3];
    __shared__ float sm2X, ssm2X, sm2P, ssm2P;

    const int w = t >> 5, lane = t & 31;

    {
        float xvX = g.xX[z][(size_t)dl * DD + t];
        float xvP = g.xP[z][(size_t)dl * DD + t];
        const float* wl = g.wlr[z] + (size_t)t * 8;
        float o[12];
#pragma unroll
        for (int i = 0; i < 6; i++) { o[i] = xvX * wl[i]; o[6 + i] = xvP * wl[i]; }
#pragma unroll
        for (int off = 16; off; off >>= 1)
#pragma unroll
            for (int i = 0; i < 12; i++) o[i] += __shfl_xor_sync(0xffffffffu, o[i], off);
        if (lane == 0)
#pragma unroll
            for (int i = 0; i < 12; i++) red[w][i] = o[i];
    }
    __syncthreads();
    float elX[3], erX[3], elP[3], erP[3];
#pragma unroll
    for (int h = 0; h < 3; h++) {
        elX[h] = red[0][h] + red[1][h] + red[2][h] + red[3][h];
        erX[h] = red[0][3 + h] + red[1][3 + h] + red[2][3 + h] + red[3][3 + h];
        elP[h] = red[0][6 + h] + red[1][6 + h] + red[2][6 + h] + red[3][6 + h];
        erP[h] = red[0][9 + h] + red[1][9 + h] + red[2][9 + h] + red[3][9 + h];
    }

    if (t < deg) {
        int s = g.adj[z][(size_t)dl * CAP + t];
        ssrc[t] = s;
        float ex[3], ep[3];
        if (s < EXER_N) {
            const float* el = g.elE[z] + (size_t)s * 4;
#pragma unroll
            for (int h = 0; h < 3; h++) { ex[h] = el[h] + erX[h]; ep[h] = el[h] + erP[h]; }
        } else {
#pragma unroll
            for (int h = 0; h < 3; h++) { ex[h] = elX[h] + erX[h]; ep[h] = elP[h] + erP[h]; }
        }
#pragma unroll
        for (int h = 0; h < 3; h++) {
            seX[t * 3 + h] = ex[h] > 0.f ? ex[h] : 0.2f * ex[h];
            seP[t * 3 + h] = ep[h] > 0.f ? ep[h] : 0.2f * ep[h];
        }
    }
    __syncthreads();

    if (w < 3) {
        float mX = -3.0e38f, mP = -3.0e38f;
        for (int j = lane; j < deg; j += 32) {
            mX = fmaxf(mX, seX[j * 3 + w]);
            mP = fmaxf(mP, seP[j * 3 + w]);
        }
#pragma unroll
        for (int off = 16; off; off >>= 1) {
            mX = fmaxf(mX, __shfl_xor_sync(0xffffffffu, mX, off));
            mP = fmaxf(mP, __shfl_xor_sync(0xffffffffu, mP, off));
        }
        float sX = 0.f, sP = 0.f;
        for (int j = lane; j < deg; j += 32) {
            sX += expf(seX[j * 3 + w] - mX);
            sP += expf(seP[j * 3 + w] - mP);
        }
#pragma unroll
        for (int off = 16; off; off >>= 1) {
            sX += __shfl_xor_sync(0xffffffffu, sX, off);
            sP += __shfl_xor_sync(0xffffffffu, sP, off);
        }
        if (lane == 0) { smX[w] = mX; ssumX[w] = sX; smP[w] = mP; ssumP[w] = sP; }
    }
    __syncthreads();
    if (t < deg) {
#pragma unroll
        for (int h = 0; h < 3; h++) {
            seX[t * 3 + h] = expf(seX[t * 3 + h] - smX[h]) / ssumX[h];
            seP[t * 3 + h] = expf(seP[t * 3 + h] - smP[h]) / ssumP[h];
        }
    }
    __syncthreads();

    const __nv_bfloat16* zE3 = g.zE3[z];
    const float* zX3 = g.zS3X[z] + (size_t)dl * HD;
    const float* zP3 = g.zS3P[z] + (size_t)dl * HD;
    const float xs0 = zX3[t], xs1 = zX3[DD + t], xs2 = zX3[2 * DD + t];
    const float ps0 = zP3[t], ps1 = zP3[DD + t], ps2 = zP3[2 * DD + t];
    float accX = 0.f, accP = 0.f;
    for (int j = 0; j < deg; j++) {
        int s = ssrc[j];
        float wx0 = seX[j * 3 + 0], wx1 = seX[j * 3 + 1], wx2 = seX[j * 3 + 2];
        float wp0 = seP[j * 3 + 0], wp1 = seP[j * 3 + 1], wp2 = seP[j * 3 + 2];
        if (s < EXER_N) {
            const __nv_bfloat16* b = zE3 + (size_t)s * HD;
            float v0 = __bfloat162float(b[t]);
            float v1 = __bfloat162float(b[DD + t]);
            float v2 = __bfloat162float(b[2 * DD + t]);
            accX += wx0 * v0 + wx1 * v1 + wx2 * v2;
            accP += wp0 * v0 + wp1 * v1 + wp2 * v2;
        } else {
            accX += wx0 * xs0 + wx1 * xs1 + wx2 * xs2;
            accP += wp0 * ps0 + wp1 * ps1 + wp2 * ps2;
        }
    }
    const float bzv = g.bz[z][t];
    const float zvX = accX + bzv;
    const float zvP = accP + bzv;

    {
        const float* aw = g.aW[z];
        float o[4] = {zvX * aw[t], zvX * aw[DD + t], zvP * aw[t], zvP * aw[DD + t]};
#pragma unroll
        for (int off = 16; off; off >>= 1)
#pragma unroll
            for (int i = 0; i < 4; i++) o[i] += __shfl_xor_sync(0xffffffffu, o[i], off);
        __syncthreads();
        if (lane == 0)
#pragma unroll
            for (int i = 0; i < 4; i++) red[w][i] = o[i];
    }
    __syncthreads();
    const float zlX = red[0][0] + red[1][0] + red[2][0] + red[3][0];
    const float zrX = red[0][1] + red[1][1] + red[2][1] + red[3][1];
    const float zlP = red[0][2] + red[1][2] + red[2][2] + red[3][2];
    const float zrP = red[0][3] + red[1][3] + red[2][3] + red[3][3];

    if (t < deg) {
        int s = ssrc[t];
        if (s < EXER_N) {
            float zl = g.zlE[z][s];
            se2X[t] = zl + zrX;
            se2P[t] = zl + zrP;
        } else {
            se2X[t] = zlX + zrX;
            se2P[t] = zlP + zrP;
        }
    }
    __syncthreads();
    if (w < 2) {
        float* se2 = (w == 0) ? se2X : se2P;
        float m = -3.0e38f;
        for (int j2 = lane; j2 < deg; j2 += 32) m = fmaxf(m, se2[j2]);
#pragma unroll
        for (int off = 16; off; off >>= 1) m = fmaxf(m, __shfl_xor_sync(0xffffffffu, m, off));
        float s = 0.f;
        for (int j2 = lane; j2 < deg; j2 += 32) s += expf(se2[j2] - m);
#pragma unroll
        for (int off = 16; off; off >>= 1) s += __shfl_xor_sync(0xffffffffu, s, off);
        if (lane == 0) {
            if (w == 0) { sm2X = m; ssm2X = s; }
            else        { sm2P = m; ssm2P = s; }
        }
    }
    __syncthreads();
    if (t < deg) {
        se2X[t] = expf(se2X[t] - sm2X) / ssm2X;
        se2P[t] = expf(se2P[t] - sm2P) / ssm2P;
    }
    __syncthreads();

    const __nv_bfloat16* zE = g.zE[z];
    float acc2X = 0.f, acc2P = 0.f;
    for (int j = 0; j < deg; j++) {
        int s = ssrc[j];
        if (s < EXER_N) {
            float v = __bfloat162float(zE[(size_t)s * DD + t]);
            acc2X += se2X[j] * v;
            acc2P += se2P[j] * v;
        } else {
            acc2X += se2X[j] * zvX;
            acc2P += se2P[j] * zvP;
        }
    }
    g.outX[z][(size_t)dl * ldo + t] = acc2X;
    g.outP[z][(size_t)dl * ldo + t] = acc2P;
}

// SSL ------------------------------------------------------------------------
__global__ void norm_rows_b(NRB g, const int* __restrict__ ids) {
    int z = blockIdx.y;
    int i = blockIdx.x, t = threadIdx.x;
    int r = ids[i];
    float v = g.emb[z][(size_t)r * DD + t];
    float sq = v * v;
#pragma unroll
    for (int off = 16; off; off >>= 1) sq += __shfl_xor_sync(0xffffffffu, sq, off);
    __shared__ float w4[4];
    if ((t & 31) == 0) w4[t >> 5] = sq;
    __syncthreads();
    float tot = w4[0] + w4[1] + w4[2] + w4[3];
    float nrm = sqrtf(tot);
    g.out[z][(size_t)i * DD + t] = v / fmaxf(nrm, 1e-12f);
}

__global__ void colsum_part(const float* __restrict__ nbp, float* __restrict__ part) {
    int b = blockIdx.x, t = threadIdx.x;
    float s = 0.f;
    const int i0 = b * (BATCH / 16);
#pragma unroll 4
    for (int i = i0; i < i0 + BATCH / 16; i++) s += nbp[(size_t)i * DD + t];
    part[b * DD + t] = s;
}
__global__ void colsum_fin(const float* __restrict__ part, float* __restrict__ S) {
    int t = threadIdx.x;
    float s = 0.f;
#pragma unroll
    for (int b = 0; b < 16; b++) s += part[b * DD + t];
    S[t] = s;
}

__global__ void loss_part(const float* __restrict__ nb, const float* __restrict__ nbp,
                          const float* __restrict__ S, float* __restrict__ lp) {
    const int w = threadIdx.x >> 5, lane = threadIdx.x & 31;
    const int i = blockIdx.x * 8 + w;
    const float4 xv = *(const float4*)(nb  + (size_t)i * DD + lane * 4);
    const float4 yv = *(const float4*)(nbp + (size_t)i * DD + lane * 4);
    const float4 sv = *(const float4*)(S + lane * 4);
    float dg = xv.x * yv.x + xv.y * yv.y + xv.z * yv.z + xv.w * yv.w;
    float rs = xv.x * sv.x + xv.y * sv.y + xv.z * sv.z + xv.w * sv.w;
#pragma unroll
    for (int off = 16; off; off >>= 1) {
        dg += __shfl_xor_sync(0xffffffffu, dg, off);
        rs += __shfl_xor_sync(0xffffffffu, rs, off);
    }
    if (lane == 0) {
        float divided = expf(dg * 5.0f) / (rs * 5.0f + 1e-8f);
        lp[i] = -logf(fmaxf(divided, 1e-8f));
    }
}
__global__ void loss_fin(const float* __restrict__ lp, float* __restrict__ out) {
    int t = threadIdx.x;
    float s = 0.f;
#pragma unroll
    for (int k = 0; k < BATCH / 256; k++) s += lp[t + k * 256];
    __shared__ float red[256];
    red[t] = s;
    __syncthreads();
    for (int st = 128; st; st >>= 1) { if (t < st) red[t] += red[t + st]; __syncthreads(); }
    if (t == 0) out[0] = red[0];
}

// ---------------- host orchestration ------------------------------------------
extern "C" void kernel_launch(void* const* d_in, const int* in_sizes, int n_in,
                              void* d_out_, int out_size)
{
    const float* stu_table  = (const float*)d_in[0];
    const float* exer_table = (const float*)d_in[1];
    const float* gat_W  = (const float*)d_in[2];
    const float* attn_l = (const float*)d_in[3];
    const float* attn_r = (const float*)d_in[4];
    const float* gat_b  = (const float*)d_in[5];
    const float* fc_W   = (const float*)d_in[6];
    const float* fc_b   = (const float*)d_in[7];
    const float* aW     = (const float*)d_in[8];
    const float* f1W    = (const float*)d_in[9];
    const float* f1b    = (const float*)d_in[10];
    const float* f2W    = (const float*)d_in[11];
    const float* f2b    = (const float*)d_in[12];
    const int* e_src[3] = {(const int*)d_in[13], (const int*)d_in[15], (const int*)d_in[21]};
    const int* e_dst[3] = {(const int*)d_in[14], (const int*)d_in[16], (const int*)d_in[22]};
    int e_n[3] = {in_sizes[13], in_sizes[15], in_sizes[21]};
    const int* stu_id = (const int*)d_in[23];
    float* d_out = (float*)d_out_;
    (void)n_in;

    float* FA = nullptr; int* IA = nullptr; __nv_bfloat16* HA = nullptr;
    cudaGetSymbolAddress((void**)&FA, g_farena);
    cudaGetSymbolAddress((void**)&IA, g_iarena);
    cudaGetSymbolAddress((void**)&HA, g_harena);

    float* Wz3   = FA + O_Wz3;
    float* Wzc   = FA + O_Wzc;
    float* Wlr   = FA + O_Wlr;
    float* bz    = FA + O_bz;
    float* zE    = FA + O_zE;
    float* elE   = FA + O_elE;
    float* zlE   = FA + O_zlE;
    float* erD   = FA + O_erD;
    float* zrD   = FA + O_zrD;
    float* ABCD  = FA + O_ABCD;
    float* ABPCD = FA + O_ABPCD;
    float* stu1  = FA + O_stu1;
    float* stu1p = FA + O_stu1p;
    float* XYX   = FA + O_XYX;
    float* XYP   = FA + O_XYP;
    float* stu2  = FA + O_stu2;
    float* stu2p = FA + O_stu2p;
    float* nb    = FA + O_nb;
    float* nbp   = FA + O_nbp;
    float* Sv    = FA + O_S;
    float* lossD = FA + O_lossd;
    float* partV = FA + O_part;
    float* lpart = FA + O_lpart;
    __nv_bfloat16* zE3h = HA + OH_zE3;
    __nv_bfloat16* zEh  = HA + OH_zE;

    const int pidx[3] = {0, 1, 4};
    const int gM_E = (EXER_N + 127) / 128;
    const int gM_S = (STU_N + 127) / 128;

    auto scr  = [&](int sc, size_t off) { return FA + O_SCR + (size_t)sc * SC_TOT + off; };
    auto adjP = [&](int s) { return IA + OI_adj + (size_t)s * STU_N * CAP; };
    auto cntP = [&](int s) { return IA + OI_cnt + (size_t)s * STU_N; };

    // ---- weight precompute + adjacency ----
    wz_kernel<<<dim3(DD, 5), DD>>>(gat_W, fc_W, Wz3, Wzc);
    wlr_kernel<<<5, DD>>>(gat_W, attn_l, attn_r, Wlr);
    bz_kernel<<<5, DD>>>(gat_b, fc_W, fc_b, bz);
    zero_int<<<(3 * STU_N + 255) / 256, 256>>>(IA + OI_cnt, 3 * STU_N);
    {
        ADJB g{};
        int max_e = 0;
        for (int s = 0; s < 3; s++) {
            g.src[s] = e_src[s]; g.dst[s] = e_dst[s]; g.ecnt[s] = e_n[s];
            g.adj[s] = adjP(s);  g.cnt[s] = cntP(s);
            if (e_n[s] > max_e) max_e = e_n[s];
        }
        build_adj_b<<<dim3((max_e + 255) / 256, 3), 256>>>(g);
    }

    // ---- phase A: exer-side invariants ----
    {
        GB g{};   // zE3 (bf16 only)
        for (int s = 0; s < 3; s++) {
            g.A[s] = exer_table;
            g.B[s] = Wz3 + (size_t)pidx[s] * DD * HD;
            g.Ch[s] = zE3h + (size_t)s * EXER_N * HD;
        }
        tgemm_b<<<dim3(HD / 128, gM_E, 3), 256>>>(g, DD, HD, 0, EXER_N, HD, DD);
    }
    {
        GB g{};   // zE fp32 (for zl reduction) + bf16 (for gathers)
        for (int s = 0; s < 3; s++) {
            g.A[s] = exer_table;
            g.B[s] = Wzc + (size_t)pidx[s] * DD * DD;
            g.C[s] = zE + (size_t)s * EXER_N * DD;
            g.Ch[s] = zEh + (size_t)s * EXER_N * DD;
            g.bias[s] = bz + (size_t)pidx[s] * DD;
        }
        tgemm_b<<<dim3(1, gM_E, 3), 256>>>(g, DD, DD, 0, EXER_N, DD, DD);
    }
    {
        EZB g{};  // fused escore + zlzr (one launch instead of two)
        for (int s = 0; s < 3; s++) {
            g.x[s]   = exer_table;
            g.wlr[s] = Wlr + (size_t)pidx[s] * DD * 8;
            g.z[s]   = zE + (size_t)s * EXER_N * DD;
            g.aW[s]  = aW + (size_t)pidx[s] * 2 * DD;
            g.el[s]  = elE + (size_t)s * EXER_N * 4;
            g.er[s]  = erD;
            g.zl[s]  = zlE + (size_t)s * EXER_N;
            g.zr[s]  = zrD;
        }
        ezl_b<<<dim3(EXER_N, 3), 128>>>(g);
    }

    // ---- layers 2,3: single GEMM, dual-store ----
    {
        GB g{};
        for (int i = 0; i < 2; i++) {
            int coff = (i == 0) ? 2 * DD : 3 * DD;
            g.A[i] = stu_table;
            g.B[i] = Wzc + (size_t)(2 + i) * DD * DD;
            g.C[i] = ABCD + coff;
            g.C2[i] = ABPCD + coff;
            g.bias[i] = bz + (size_t)(2 + i) * DD;
        }
        tgemm_b<<<dim3(1, gM_S, 2), 256>>>(g, DD, 4 * DD, 0, STU_N, DD, DD);
    }

    // ---- phase B: zS3 GEMM + one fused GAT launch (z=3) ----
    {
        const int slot[3] = {0, 1, 2};
        {
            GB g{};
            for (int i = 0; i < 3; i++) {
                g.A[i] = stu_table;
                g.B[i] = Wz3 + (size_t)pidx[slot[i]] * DD * HD;
                g.C[i] = scr(i, SC_zS3);
            }
            tgemm_b<<<dim3(HD / 128, gM_S, 3), 256>>>(g, DD, HD, 0, STU_N, HD, DD);
        }
        {
            FZB g{};
            float* outb[3]  = {ABCD, ABCD + DD, ABPCD + DD};
            float* outb2[3] = {ABPCD, nullptr, nullptr};
            for (int i = 0; i < 3; i++) {
                int s = slot[i];
                g.adj[i] = adjP(s); g.cnt[i] = cntP(s);
                g.x[i]   = stu_table;
                g.wlr[i] = Wlr + (size_t)pidx[s] * DD * 8;
                g.elE[i] = elE + (size_t)s * EXER_N * 4;
                g.zE3[i] = zE3h + (size_t)s * EXER_N * HD;
                g.zS3[i] = scr(i, SC_zS3);
                g.zE[i]  = zEh + (size_t)s * EXER_N * DD;
                g.zlE[i] = zlE + (size_t)s * EXER_N;
                g.bz[i]  = bz + (size_t)pidx[s] * DD;
                g.aW[i]  = aW + (size_t)pidx[s] * 2 * DD;
                g.out[i]  = outb[i];
                g.out2[i] = outb2[i];
            }
            gat_fused_b<<<dim3(STU_N, 3), 128>>>(g, 4 * DD);
        }
    }

    // ---- fuse1: K=512 GEMM + residual ----
    {
        GB g{};
        g.A[0] = ABCD;  g.C[0] = stu1;  g.bias[0] = f1b; g.addm[0] = stu_table;
        g.A[1] = ABPCD; g.C[1] = stu1p; g.bias[1] = f1b; g.addm[1] = stu_table;
        g.B[0] = f1W; g.B[1] = f1W;
        tgemm_b<<<dim3(1, gM_S, 2), 256>>>(g, 4 * DD, DD, DD, STU_N, DD, 4 * DD);
    }

    // ---- phase D: zS3 GEMM (z=4) + one merged fused GAT (z=2) ----
    {
        const float* xS[4] = {stu1, stu1, stu1p, stu1p};
        const int slot4[4] = {0, 1, 0, 1};
        {
            GB g{};
            for (int i = 0; i < 4; i++) {
                g.A[i] = xS[i];
                g.B[i] = Wz3 + (size_t)pidx[slot4[i]] * DD * HD;
                g.C[i] = scr(i, SC_zS3);
            }
            tgemm_b<<<dim3(HD / 128, gM_S, 4), 256>>>(g, DD, HD, 0, STU_N, HD, DD);
        }
        {
            FZM g{};
            for (int s = 0; s < 2; s++) {
                g.adj[s] = adjP(s); g.cnt[s] = cntP(s);
                g.wlr[s] = Wlr + (size_t)pidx[s] * DD * 8;
                g.elE[s] = elE + (size_t)s * EXER_N * 4;
                g.zE3[s] = zE3h + (size_t)s * EXER_N * HD;
                g.zE[s]  = zEh + (size_t)s * EXER_N * DD;
                g.zlE[s] = zlE + (size_t)s * EXER_N;
                g.bz[s]  = bz + (size_t)pidx[s] * DD;
                g.aW[s]  = aW + (size_t)pidx[s] * 2 * DD;
                g.xX[s]  = stu1;  g.xP[s] = stu1p;
                g.zS3X[s] = scr(s, SC_zS3);
                g.zS3P[s] = scr(s + 2, SC_zS3);
                g.outX[s] = XYX + (size_t)s * DD;
                g.outP[s] = XYP + (size_t)s * DD;
            }
            gat_fused_m<<<dim3(STU_N, 2), 128>>>(g, 2 * DD);
        }
    }

    // ---- fusion2: K=256 + residual; stu2 dual-stored to d_out ----
    const int NOUT = STU_N * DD;
    {
        GB g{};
        g.A[0] = XYX; g.C[0] = stu2;  g.bias[0] = f2b; g.addm[0] = stu1;
        g.A[1] = XYP; g.C[1] = stu2p; g.bias[1] = f2b; g.addm[1] = stu1p;
        g.B[0] = f2W; g.B[1] = f2W;
        if (out_size >= NOUT) g.C2[0] = d_out;
        tgemm_b<<<dim3(1, gM_S, 2), 256>>>(g, 2 * DD, DD, DD, STU_N, DD, 2 * DD);
    }

    float* lossdst = lossD;
    if (out_size == 1) lossdst = d_out;
    else if (out_size > NOUT) lossdst = d_out + (out_size - 1);

    {
        NRB g{};
        g.emb[0] = stu2;  g.out[0] = nb;
        g.emb[1] = stu2p; g.out[1] = nbp;
        norm_rows_b<<<dim3(BATCH, 2), 128>>>(g, stu_id);
    }
    colsum_part<<<16, 128>>>(nbp, partV);
    colsum_fin<<<1, 128>>>(partV, Sv);
    loss_part<<<BATCH / 8, 256>>>(nb, nbp, Sv, lpart);
    loss_fin<<<1, 256>>>(lpart, lossdst);
}